// round 4
// baseline (speedup 1.0000x reference)
#include <cuda_runtime.h>
#include <cstdint>

// ---------------- problem constants ----------------
static constexpr int NF = 8192;          // output features (N)
static constexpr int NX = 2048;          // reduction (K)
static constexpr int MM = 8192;          // rows of x (M) = 4*2048

static constexpr int BM = 256;           // M tile
static constexpr int BN = 128;           // N tile
static constexpr int BK = 32;            // K per stage (32 fp32 = 128B per row)
static constexpr int STAGES = 3;
static constexpr int KITERS = NX / BK;   // 64
static constexpr int THREADS = 512;      // 16 warps: 4 (M) x 4 (N)

static constexpr int A_BYTES = BM * 128;             // 32768
static constexpr int B_BYTES = BN * 128;             // 16384
static constexpr int STAGE_BYTES = A_BYTES + B_BYTES;// 49152
static constexpr int SMEM_TOTAL = STAGES * STAGE_BYTES; // 147456

// 64MB tf32-rounded W scratch + 64MB tf32-rounded x scratch (device globals: allowed)
__device__ float g_W[(size_t)NF * NX];
__device__ float g_X[(size_t)MM * NX];

// ---------------- helpers (sm_80-level PTX only; nothing 'a'-gated) ----------------
__device__ __forceinline__ uint32_t smem_u32(const void* p) {
    uint32_t a;
    asm("{ .reg .u64 t; cvta.to.shared.u64 t, %1; cvt.u32.u64 %0, t; }" : "=r"(a) : "l"(p));
    return a;
}
__device__ __forceinline__ void cp16(uint32_t dst, const void* src) {
    asm volatile("cp.async.cg.shared.global [%0], [%1], 16;" :: "r"(dst), "l"(src) : "memory");
}
__device__ __forceinline__ void cp_commit() {
    asm volatile("cp.async.commit_group;" ::: "memory");
}
template <int N>
__device__ __forceinline__ void cp_wait_group() {
    asm volatile("cp.async.wait_group %0;" :: "n"(N) : "memory");
}
__device__ __forceinline__ float tf32r(float f) {
    uint32_t u;
    asm("cvt.rna.tf32.f32 %0, %1;" : "=r"(u) : "f"(f));
    return __uint_as_float(u);
}
__device__ __forceinline__ void ldsm4(uint32_t* r, uint32_t addr) {
    asm volatile("ldmatrix.sync.aligned.m8n8.x4.shared.b16 {%0,%1,%2,%3}, [%4];"
                 : "=r"(r[0]), "=r"(r[1]), "=r"(r[2]), "=r"(r[3]) : "r"(addr));
}
__device__ __forceinline__ void lds32(uint32_t& v, uint32_t addr) {
    asm volatile("ld.shared.b32 %0, [%1];" : "=r"(v) : "r"(addr));
}
__device__ __forceinline__ void mma8(float* c, const uint32_t* a, uint32_t b0, uint32_t b1) {
    asm volatile(
        "mma.sync.aligned.m16n8k8.row.col.f32.tf32.tf32.f32 "
        "{%0,%1,%2,%3}, {%4,%5,%6,%7}, {%8,%9}, {%0,%1,%2,%3};"
        : "+f"(c[0]), "+f"(c[1]), "+f"(c[2]), "+f"(c[3])
        : "r"(a[0]), "r"(a[1]), "r"(a[2]), "r"(a[3]), "r"(b0), "r"(b1));
}

// ---------------- prep: round x to tf32 into g_X ----------------
__global__ void __launch_bounds__(256) prep_x_kernel(const float4* __restrict__ x) {
    int i = blockIdx.x * 256 + threadIdx.x;
    float4 v = x[i];
    v.x = tf32r(v.x); v.y = tf32r(v.y); v.z = tf32r(v.z); v.w = tf32r(v.w);
    reinterpret_cast<float4*>(g_X)[i] = v;
}

// ---------------- dequant: packed int4 -> tf32-rounded fp32 g_W ----------------
__global__ void __launch_bounds__(256) dequant_kernel(
    const int* __restrict__ packed,
    const float* __restrict__ scales,
    const int* __restrict__ zeros)
{
    int t = blockIdx.x * 256 + threadIdx.x;     // handles 4 int32 (bytes) = 8 weights
    int f  = t >> 8;                            // 256 chunks of 4 packed cols per row
    int jc = (t & 255) * 4;                     // packed-col base (0..1020)
    int4 p = reinterpret_cast<const int4*>(packed)[t];
    int g = jc >> 5;                            // group = (jc*2)/64
    float s = scales[f * 32 + g];
    float z = (float)zeros[f * 32 + g];

    float4 w0, w1;
    int v;
    v = p.x; w0.x = tf32r(((v & 15) - z) * s);  w0.y = tf32r((((v >> 4) & 15) - z) * s);
    v = p.y; w0.z = tf32r(((v & 15) - z) * s);  w0.w = tf32r((((v >> 4) & 15) - z) * s);
    v = p.z; w1.x = tf32r(((v & 15) - z) * s);  w1.y = tf32r((((v >> 4) & 15) - z) * s);
    v = p.w; w1.z = tf32r(((v & 15) - z) * s);  w1.w = tf32r((((v >> 4) & 15) - z) * s);

    float4* dst = reinterpret_cast<float4*>(g_W + (size_t)f * NX + jc * 2);
    dst[0] = w0;
    dst[1] = w1;
}

// ---------------- tf32 mma.sync GEMM: out = x @ W^T + bias ----------------
__global__ void __launch_bounds__(THREADS, 1) gemm_kernel(
    const float* __restrict__ bias,
    float* __restrict__ out)
{
    extern __shared__ __align__(1024) char smem[];
    uint32_t sb = smem_u32(smem);
    const int tid  = threadIdx.x;
    const int lane = tid & 31;
    const int wid  = tid >> 5;
    const int warp_m = wid & 3;   // 0..3 -> 64-row slabs
    const int warp_n = wid >> 2;  // 0..3 -> 32-col slabs

    // L2-friendly rasterization: supergroups of 8 M-tiles across all N
    const int GRID_N = NF / BN;              // 64
    const int GROUP_M = 8;
    const int nig = GROUP_M * GRID_N;        // 512
    int pid = blockIdx.x;
    int pm = (pid / nig) * GROUP_M + (pid % nig) % GROUP_M;
    int pn = (pid % nig) / GROUP_M;
    int m0 = pm * BM;
    int n0 = pn * BN;

    // ---- producer addressing (all 512 threads) ----
    const int pc = tid & 7;                  // 16B granule in row
    const int pr = tid >> 3;                 // row 0..63 (per pass)
    const float* aSrc = g_X + (size_t)(m0 + pr) * NX + pc * 4;
    const float* bSrc = g_W + (size_t)(n0 + pr) * NX + pc * 4;
    const uint32_t swz = (uint32_t)(pr * 128) + ((uint32_t)(pc ^ (pr & 7)) << 4);

    auto issue = [&](int kb, int st) {
        uint32_t base = sb + st * STAGE_BYTES + swz;
        const float* as = aSrc + kb * BK;
        #pragma unroll
        for (int p = 0; p < 4; p++)                       // A: 256 rows
            cp16(base + p * 8192, as + (size_t)p * 64 * NX);
        const float* bs = bSrc + kb * BK;
        #pragma unroll
        for (int p = 0; p < 2; p++)                       // B: 128 rows
            cp16(base + A_BYTES + p * 8192, bs + (size_t)p * 64 * NX);
    };

    // ---- consumer addressing ----
    const uint32_t h = lane >> 4;            // 0/1 -> k-granule half for ldmatrix
    uint32_t abase[4], arx[4];
    #pragma unroll
    for (int tm = 0; tm < 4; tm++) {
        uint32_t row = warp_m * 64 + tm * 16 + ((lane >> 3) & 1) * 8 + (lane & 7);
        abase[tm] = row * 128;
        arx[tm] = row & 7;
    }
    const uint32_t group = lane >> 2;        // n within n8 / row group
    const uint32_t tig   = lane & 3;         // k within k4 / col pair
    uint32_t bbase[4];
    #pragma unroll
    for (int j = 0; j < 4; j++) {
        uint32_t n = warp_n * 32 + j * 8 + group;
        bbase[j] = A_BYTES + n * 128 + tig * 4;
    }

    float acc[4][4][4];
    #pragma unroll
    for (int tm = 0; tm < 4; tm++)
        #pragma unroll
        for (int j = 0; j < 4; j++)
            #pragma unroll
            for (int q = 0; q < 4; q++) acc[tm][j][q] = 0.0f;

    // ---- prologue: 2 stages in flight ----
    issue(0, 0); cp_commit();
    issue(1, 1); cp_commit();

    // ---- mainloop ----
    #pragma unroll 1
    for (int kb = 0; kb < KITERS; kb++) {
        cp_wait_group<1>();
        __syncthreads();
        if (kb + 2 < KITERS) issue(kb + 2, (kb + 2) % STAGES);
        cp_commit();

        uint32_t stb = sb + (kb % STAGES) * STAGE_BYTES;
        #pragma unroll
        for (int s = 0; s < 4; s++) {
            uint32_t a[4][4];
            #pragma unroll
            for (int tm = 0; tm < 4; tm++)
                ldsm4(a[tm], stb + abase[tm] + (((2u * s + h) ^ arx[tm]) << 4));

            const uint32_t g0 = ((2u * s)     ^ group) << 4;
            const uint32_t g1 = ((2u * s + 1) ^ group) << 4;
            uint32_t b0[4], b1[4];
            #pragma unroll
            for (int j = 0; j < 4; j++) {
                lds32(b0[j], stb + bbase[j] + g0);
                lds32(b1[j], stb + bbase[j] + g1);
            }
            #pragma unroll
            for (int tm = 0; tm < 4; tm++)
                #pragma unroll
                for (int j = 0; j < 4; j++)
                    mma8(acc[tm][j], a[tm], b0[j], b1[j]);
        }
    }

    // ---- epilogue: +bias, store ----
    const float* bp = bias + n0 + warp_n * 32 + 2 * tig;
    float2 bv[4];
    #pragma unroll
    for (int j = 0; j < 4; j++)
        bv[j] = *reinterpret_cast<const float2*>(bp + j * 8);

    #pragma unroll
    for (int tm = 0; tm < 4; tm++) {
        int row = m0 + warp_m * 64 + tm * 16 + (int)group;
        float* o0 = out + (size_t)row * NF + n0 + warp_n * 32 + 2 * tig;
        float* o1 = o0 + (size_t)8 * NF;
        #pragma unroll
        for (int j = 0; j < 4; j++) {
            float2 v0, v1;
            v0.x = acc[tm][j][0] + bv[j].x;
            v0.y = acc[tm][j][1] + bv[j].y;
            v1.x = acc[tm][j][2] + bv[j].x;
            v1.y = acc[tm][j][3] + bv[j].y;
            *reinterpret_cast<float2*>(o0 + j * 8) = v0;
            *reinterpret_cast<float2*>(o1 + j * 8) = v1;
        }
    }
}

// ---------------- launch ----------------
extern "C" void kernel_launch(void* const* d_in, const int* in_sizes, int n_in,
                              void* d_out, int out_size)
{
    (void)in_sizes; (void)n_in; (void)out_size;
    const float* x      = (const float*)d_in[0];
    const int*   packed = (const int*)  d_in[1];
    const float* scales = (const float*)d_in[2];
    const int*   zeros  = (const int*)  d_in[3];
    const float* bias   = (const float*)d_in[4];
    float* out = (float*)d_out;

    // 1) round x to tf32 (removes in-loop cvt and halves tf32 truncation error)
    prep_x_kernel<<<(MM * NX / 4) / 256, 256>>>((const float4*)x);

    // 2) dequant packed int4 -> tf32-rounded fp32 W
    dequant_kernel<<<(NF * (NX / 2) / 4) / 256, 256>>>(packed, scales, zeros);

    // 3) tf32 mma.sync GEMM
    cudaFuncSetAttribute(gemm_kernel, cudaFuncAttributeMaxDynamicSharedMemorySize, SMEM_TOTAL);
    gemm_kernel<<<(MM / BM) * (NF / BN), THREADS, SMEM_TOTAL>>>(bias, out);
}

// round 5
// speedup vs baseline: 1.9644x; 1.9644x over previous
#include <cuda_runtime.h>
#include <cuda_fp16.h>
#include <cstdint>

// ---------------- problem constants ----------------
static constexpr int NF = 8192;          // output features (N)
static constexpr int NX = 2048;          // reduction (K)
static constexpr int MM = 8192;          // rows of x (M)

static constexpr int BM = 256;           // M tile
static constexpr int BN = 128;           // N tile
static constexpr int BK = 64;            // K per stage (64 halfs = 128B per row)
static constexpr int STAGES = 3;
static constexpr int KITERS = NX / BK;   // 32
static constexpr int THREADS = 512;      // 16 warps: 4 (M) x 4 (N)

static constexpr int A_BYTES = BM * 128;              // 32768
static constexpr int B_BYTES = BN * 128;              // 16384
static constexpr int STAGE_BYTES = A_BYTES + B_BYTES; // 49152
static constexpr int SMEM_TOTAL = STAGES * STAGE_BYTES; // 147456

// 32MB fp16 W scratch + 32MB fp16 x scratch (device globals: allowed)
__device__ __half g_W[(size_t)NF * NX];
__device__ __half g_X[(size_t)MM * NX];

// ---------------- helpers (sm_80-level PTX only) ----------------
__device__ __forceinline__ uint32_t smem_u32(const void* p) {
    uint32_t a;
    asm("{ .reg .u64 t; cvta.to.shared.u64 t, %1; cvt.u32.u64 %0, t; }" : "=r"(a) : "l"(p));
    return a;
}
__device__ __forceinline__ void cp16(uint32_t dst, const void* src) {
    asm volatile("cp.async.cg.shared.global [%0], [%1], 16;" :: "r"(dst), "l"(src) : "memory");
}
__device__ __forceinline__ void cp_commit() {
    asm volatile("cp.async.commit_group;" ::: "memory");
}
template <int N>
__device__ __forceinline__ void cp_wait_group() {
    asm volatile("cp.async.wait_group %0;" :: "n"(N) : "memory");
}
__device__ __forceinline__ void ldsm4(uint32_t* r, uint32_t addr) {
    asm volatile("ldmatrix.sync.aligned.m8n8.x4.shared.b16 {%0,%1,%2,%3}, [%4];"
                 : "=r"(r[0]), "=r"(r[1]), "=r"(r[2]), "=r"(r[3]) : "r"(addr));
}
__device__ __forceinline__ void mma16(float* c, const uint32_t* a, uint32_t b0, uint32_t b1) {
    asm volatile(
        "mma.sync.aligned.m16n8k16.row.col.f32.f16.f16.f32 "
        "{%0,%1,%2,%3}, {%4,%5,%6,%7}, {%8,%9}, {%0,%1,%2,%3};"
        : "+f"(c[0]), "+f"(c[1]), "+f"(c[2]), "+f"(c[3])
        : "r"(a[0]), "r"(a[1]), "r"(a[2]), "r"(a[3]), "r"(b0), "r"(b1));
}

// ---------------- prep: x (fp32) -> fp16 g_X ----------------
__global__ void __launch_bounds__(256) prep_x_kernel(const float4* __restrict__ x) {
    int i = blockIdx.x * 256 + threadIdx.x;     // handles 8 floats -> 8 halfs (16B out)
    float4 v0 = x[2 * i];
    float4 v1 = x[2 * i + 1];
    __half2 h[4];
    h[0] = __floats2half2_rn(v0.x, v0.y);
    h[1] = __floats2half2_rn(v0.z, v0.w);
    h[2] = __floats2half2_rn(v1.x, v1.y);
    h[3] = __floats2half2_rn(v1.z, v1.w);
    reinterpret_cast<uint4*>(g_X)[i] = *reinterpret_cast<uint4*>(h);
}

// ---------------- dequant: packed int4 -> fp16 g_W ----------------
__global__ void __launch_bounds__(256) dequant_kernel(
    const int* __restrict__ packed,
    const float* __restrict__ scales,
    const int* __restrict__ zeros)
{
    int t = blockIdx.x * 256 + threadIdx.x;     // handles 4 int32 (bytes) = 8 weights
    int f  = t >> 8;                            // 256 chunks per row
    int jc = (t & 255) * 4;                     // packed-col base
    int4 p = reinterpret_cast<const int4*>(packed)[t];
    int g = jc >> 5;                            // group index
    float s = scales[f * 32 + g];
    float z = (float)zeros[f * 32 + g];

    __half2 h[4];
    int v;
    v = p.x; h[0] = __floats2half2_rn(((v & 15) - z) * s, (((v >> 4) & 15) - z) * s);
    v = p.y; h[1] = __floats2half2_rn(((v & 15) - z) * s, (((v >> 4) & 15) - z) * s);
    v = p.z; h[2] = __floats2half2_rn(((v & 15) - z) * s, (((v >> 4) & 15) - z) * s);
    v = p.w; h[3] = __floats2half2_rn(((v & 15) - z) * s, (((v >> 4) & 15) - z) * s);

    *reinterpret_cast<uint4*>(g_W + (size_t)f * NX + jc * 2) = *reinterpret_cast<uint4*>(h);
}

// ---------------- fp16 mma.sync GEMM: out = x @ W^T + bias ----------------
__global__ void __launch_bounds__(THREADS, 1) gemm_kernel(
    const float* __restrict__ bias,
    float* __restrict__ out)
{
    extern __shared__ __align__(1024) char smem[];
    uint32_t sb = smem_u32(smem);
    const int tid  = threadIdx.x;
    const int lane = tid & 31;
    const int wid  = tid >> 5;
    const int warp_m = wid & 3;   // 64-row slab
    const int warp_n = wid >> 2;  // 32-col slab

    // L2-friendly rasterization: supergroups of 8 M-tiles across all N
    const int GRID_N = NF / BN;              // 64
    const int GROUP_M = 8;
    const int nig = GROUP_M * GRID_N;        // 512
    int pid = blockIdx.x;
    int pm = (pid / nig) * GROUP_M + (pid % nig) % GROUP_M;
    int pn = (pid % nig) / GROUP_M;
    int m0 = pm * BM;
    int n0 = pn * BN;

    // ---- producer addressing (512 threads, 16B granules, 128B rows) ----
    const int pc = tid & 7;                  // granule in row
    const int pr = tid >> 3;                 // row 0..63 per pass
    const __half* aSrc = g_X + (size_t)(m0 + pr) * NX + pc * 8;
    const __half* bSrc = g_W + (size_t)(n0 + pr) * NX + pc * 8;
    const uint32_t swz = (uint32_t)(pr * 128) + ((uint32_t)(pc ^ (pr & 7)) << 4);

    auto issue = [&](int kb, int st) {
        uint32_t base = sb + st * STAGE_BYTES + swz;
        const __half* as = aSrc + kb * BK;
        #pragma unroll
        for (int p = 0; p < 4; p++)                       // A: 256 rows
            cp16(base + p * 8192, as + (size_t)p * 64 * NX);
        const __half* bs = bSrc + kb * BK;
        #pragma unroll
        for (int p = 0; p < 2; p++)                       // B: 128 rows
            cp16(base + A_BYTES + p * 8192, bs + (size_t)p * 64 * NX);
    };

    // ---- consumer addressing (ldmatrix.x4 for both A and B) ----
    const uint32_t l  = lane & 7;
    const uint32_t q  = lane >> 3;           // 0..3
    const uint32_t ql = q & 1;
    const uint32_t qh = q >> 1;

    // A x4: M0 rows m..m+7 @k0 | M1 rows m+8..15 @k0 | M2 rows m..7 @k0+8 | M3 rows m+8..15 @k0+8
    uint32_t aoff[4], arx[4];
    #pragma unroll
    for (int tm = 0; tm < 4; tm++) {
        uint32_t row = warp_m * 64 + tm * 16 + ql * 8 + l;
        aoff[tm] = row * 128;
        arx[tm]  = row & 7;
    }
    // B x4 (covers n16): M0 n..n+7 @k0 | M1 n..n+7 @k0+8 | M2 n+8..15 @k0 | M3 n+8..15 @k0+8
    uint32_t boff[2], brx[2];
    #pragma unroll
    for (int p = 0; p < 2; p++) {
        uint32_t row = warp_n * 32 + p * 16 + qh * 8 + l;
        boff[p] = A_BYTES + row * 128;
        brx[p]  = row & 7;
    }

    float acc[4][4][4];
    #pragma unroll
    for (int tm = 0; tm < 4; tm++)
        #pragma unroll
        for (int j = 0; j < 4; j++)
            #pragma unroll
            for (int qq = 0; qq < 4; qq++) acc[tm][j][qq] = 0.0f;

    // ---- prologue ----
    issue(0, 0); cp_commit();
    issue(1, 1); cp_commit();

    // ---- mainloop ----
    #pragma unroll 1
    for (int kb = 0; kb < KITERS; kb++) {
        cp_wait_group<1>();
        __syncthreads();
        if (kb + 2 < KITERS) issue(kb + 2, (kb + 2) % STAGES);
        cp_commit();

        uint32_t stb = sb + (kb % STAGES) * STAGE_BYTES;
        #pragma unroll
        for (uint32_t s = 0; s < 4; s++) {               // 4 x k16 = BK 64
            uint32_t a[4][4];
            #pragma unroll
            for (int tm = 0; tm < 4; tm++)
                ldsm4(a[tm], stb + aoff[tm] + (((2u * s + qh) ^ arx[tm]) << 4));

            uint32_t b[2][4];
            #pragma unroll
            for (int p = 0; p < 2; p++)
                ldsm4(b[p], stb + boff[p] + (((2u * s + ql) ^ brx[p]) << 4));

            #pragma unroll
            for (int tm = 0; tm < 4; tm++)
                #pragma unroll
                for (int p = 0; p < 2; p++) {
                    mma16(acc[tm][2 * p],     a[tm], b[p][0], b[p][1]);
                    mma16(acc[tm][2 * p + 1], a[tm], b[p][2], b[p][3]);
                }
        }
    }

    // ---- epilogue: +bias, store ----
    const uint32_t group = lane >> 2;        // output row within 8
    const uint32_t tig   = lane & 3;         // output col pair
    const float* bp = bias + n0 + warp_n * 32 + 2 * tig;
    float2 bv[4];
    #pragma unroll
    for (int j = 0; j < 4; j++)
        bv[j] = *reinterpret_cast<const float2*>(bp + j * 8);

    #pragma unroll
    for (int tm = 0; tm < 4; tm++) {
        int row = m0 + warp_m * 64 + tm * 16 + (int)group;
        float* o0 = out + (size_t)row * NF + n0 + warp_n * 32 + 2 * tig;
        float* o1 = o0 + (size_t)8 * NF;
        #pragma unroll
        for (int j = 0; j < 4; j++) {
            float2 v0, v1;
            v0.x = acc[tm][j][0] + bv[j].x;
            v0.y = acc[tm][j][1] + bv[j].y;
            v1.x = acc[tm][j][2] + bv[j].x;
            v1.y = acc[tm][j][3] + bv[j].y;
            *reinterpret_cast<float2*>(o0 + j * 8) = v0;
            *reinterpret_cast<float2*>(o1 + j * 8) = v1;
        }
    }
}

// ---------------- launch ----------------
extern "C" void kernel_launch(void* const* d_in, const int* in_sizes, int n_in,
                              void* d_out, int out_size)
{
    (void)in_sizes; (void)n_in; (void)out_size;
    const float* x      = (const float*)d_in[0];
    const int*   packed = (const int*)  d_in[1];
    const float* scales = (const float*)d_in[2];
    const int*   zeros  = (const int*)  d_in[3];
    const float* bias   = (const float*)d_in[4];
    float* out = (float*)d_out;

    // 1) convert x to fp16
    prep_x_kernel<<<(MM * NX / 8) / 256, 256>>>((const float4*)x);

    // 2) dequant packed int4 -> fp16 W
    dequant_kernel<<<(NF * (NX / 2) / 4) / 256, 256>>>(packed, scales, zeros);

    // 3) fp16 mma.sync GEMM
    cudaFuncSetAttribute(gemm_kernel, cudaFuncAttributeMaxDynamicSharedMemorySize, SMEM_TOTAL);
    gemm_kernel<<<(MM / BM) * (NF / BN), THREADS, SMEM_TOTAL>>>(bias, out);
}